// round 16
// baseline (speedup 1.0000x reference)
#include <cuda_runtime.h>
#include <cuda_fp16.h>
#include <math.h>
#include <stdint.h>

// LSTM B=256,T=512,D=256,H=1024,C=128.
// Persistent kernel on mma.sync fp16 (single fp16 W, fp16 A), fp32 accum.
// 128 CTAs = 2 Mtiles(128) x 64 Ntiles(64).
// R11: per-mt-group barriers (2 x 64 CTAs, disjoint dependency groups),
// t+1 x-slabs staged during tail computes; W resident in smem (160KB).

#define BB   256
#define TT   512
#define DD   256
#define HH   1024
#define CCC  128
#define KTOT 1280
#define NTOT 4096
#define GRID 128
#define NTH  256
#define KBLK 64
#define NKB  (KTOT / KBLK)   // 20

// dynamic smem: W resident (20 slabs x 8KB) + FOUR A stages (16KB each)
#define OFF_W      0
#define OFF_AST    163840
#define STG_STRIDE 16384
#define SMEM_TOTAL 229376    // 163840 + 4*16384

#define SW(o) ((o) ^ (((o) >> 3) & 0x70))

// ---------------- device globals ----------------
__device__ __half g_W16[(size_t)NTOT * KTOT];
__device__ float  g_bcat[NTOT];
__device__ __half g_x16[(size_t)TT * BB * DD];
__device__ __half g_h16[2][BB * HH];   // double-buffered across steps
__device__ float  g_hf[BB * HH];
__device__ unsigned g_barg[64];        // [0] for mt=0, [32] for mt=1 (128B apart)

// ---------------- PTX helpers ----------------
__device__ __forceinline__ uint32_t smem_to_u32(const void* p) {
    uint32_t a;
    asm("{ .reg .u64 t; cvta.to.shared.u64 t, %1; cvt.u32.u64 %0, t; }" : "=r"(a) : "l"(p));
    return a;
}

#define CP16(dst, src) \
    asm volatile("cp.async.cg.shared.global [%0], [%1], 16;" :: "r"(dst), "l"(src) : "memory")
#define CP_COMMIT() asm volatile("cp.async.commit_group;" ::: "memory")
#define CP_WAIT0()  asm volatile("cp.async.wait_group 0;" ::: "memory")
#define CP_WAIT1()  asm volatile("cp.async.wait_group 1;" ::: "memory")
#define CP_WAIT2()  asm volatile("cp.async.wait_group 2;" ::: "memory")
#define CP_WAIT3()  asm volatile("cp.async.wait_group 3;" ::: "memory")

#define LDSM_X4(r0, r1, r2, r3, addr) \
    asm volatile("ldmatrix.sync.aligned.m8n8.x4.shared.b16 {%0,%1,%2,%3}, [%4];" \
                 : "=r"(r0), "=r"(r1), "=r"(r2), "=r"(r3) : "r"(addr))

#define MMA_F16(c, a, b) \
    asm volatile("mma.sync.aligned.m16n8k16.row.col.f32.f16.f16.f32 " \
                 "{%0,%1,%2,%3},{%4,%5,%6,%7},{%8,%9},{%0,%1,%2,%3};" \
                 : "+f"((c)[0]), "+f"((c)[1]), "+f"((c)[2]), "+f"((c)[3]) \
                 : "r"((a)[0]), "r"((a)[1]), "r"((a)[2]), "r"((a)[3]), \
                   "r"((b)[0]), "r"((b)[1]))

// ---------------- column interleave mapping ----------------
// Within each 32-col warp tile: col(u,g) = 16*(u>>2) + 8*(g>>1) + 2*(u&3) + (g&1)
// => u = ((o>>4)<<2) + ((o>>1)&3),  g = ((o>>3)&1)*2 + (o&1)
// Global: n = w32*32 + o,  hidden j = w32*8 + u.

// ---------------- init kernels ----------------
__global__ void pack_w_kernel(
    const float* __restrict__ Wgx, const float* __restrict__ Wgh,
    const float* __restrict__ Wix, const float* __restrict__ Wih,
    const float* __restrict__ Wfx, const float* __restrict__ Wfh,
    const float* __restrict__ Wox, const float* __restrict__ Woh,
    const float* __restrict__ bg,  const float* __restrict__ bi,
    const float* __restrict__ bf,  const float* __restrict__ bo)
{
    const long total = (long)NTOT * KTOT;
    for (long idx = (long)blockIdx.x * blockDim.x + threadIdx.x; idx < total;
         idx += (long)gridDim.x * blockDim.x) {
        int n = (int)(idx / KTOT);
        int k = (int)(idx % KTOT);
        int o = n & 31;
        int w32 = n >> 5;
        int u = ((o >> 4) << 2) + ((o >> 1) & 3);
        int g = ((o >> 3) & 1) * 2 + (o & 1);
        int j = w32 * 8 + u;
        float w;
        if (k < DD) {
            const float* src = (g == 0) ? Wgx : (g == 1) ? Wix : (g == 2) ? Wfx : Wox;
            w = src[(size_t)k * HH + j];
        } else {
            const float* src = (g == 0) ? Wgh : (g == 1) ? Wih : (g == 2) ? Wfh : Woh;
            w = src[(size_t)(k - DD) * HH + j];
        }
        g_W16[idx] = __float2half_rn(w);

        if (idx < NTOT) {
            int nb  = (int)idx;
            int ob  = nb & 31;
            int wb  = nb >> 5;
            int ub  = ((ob >> 4) << 2) + ((ob >> 1) & 3);
            int gb  = ((ob >> 3) & 1) * 2 + (ob & 1);
            int jb  = wb * 8 + ub;
            const float* bsrc = (gb == 0) ? bg : (gb == 1) ? bi : (gb == 2) ? bf : bo;
            g_bcat[nb] = bsrc[jb];
        }
        if (idx < (long)BB * HH) {
            g_h16[0][idx] = __float2half_rn(0.0f);
            g_h16[1][idx] = __float2half_rn(0.0f);
        }
        if (idx < 64) g_barg[idx] = 0u;
    }
}

__global__ void pack_x_kernel(const float* __restrict__ x)
{
    const long total = (long)TT * BB * DD;
    for (long idx = (long)blockIdx.x * blockDim.x + threadIdx.x; idx < total;
         idx += (long)gridDim.x * blockDim.x) {
        int t = (int)(idx / (BB * DD));
        int r = (int)(idx % (BB * DD));
        int b = r / DD;
        int d = r % DD;
        g_x16[idx] = __float2half_rn(x[((size_t)b * TT + t) * DD + d]);
    }
}

// ---------------- split per-group grid barrier ----------------
__device__ __forceinline__ void grid_arrive(unsigned* bar)
{
    // caller must __syncthreads() before this so all CTA writes precede release
    if (threadIdx.x == 0)
        asm volatile("red.release.gpu.global.add.u32 [%0], %1;" :: "l"(bar), "r"(1u) : "memory");
}
__device__ __forceinline__ void grid_wait(unsigned* bar, unsigned target)
{
    if (threadIdx.x == 0) {
        unsigned v;
        do {
            asm volatile("ld.acquire.gpu.global.u32 %0, [%1];" : "=r"(v) : "l"(bar) : "memory");
        } while (v < target);
    }
    __syncthreads();
}

__device__ __forceinline__ float sigf(float x) { return 1.0f / (1.0f + __expf(-x)); }
__device__ __forceinline__ float tanhfast(float x) { return 2.0f * sigf(2.0f * x) - 1.0f; }

// ---------------- A staging: gmem -> smem via cp.async (A only) ----------------
__device__ __forceinline__ void stage_A(uint32_t sb, int t, int m0, int k0, int tid,
                                        const __half* __restrict__ hrd)
{
#pragma unroll
    for (int i = 0; i < 4; i++) {
        int idx = tid + i * NTH;       // 0..1023
        int row = idx >> 3;            // 0..127
        int q   = idx & 7;
        const __half* ph;
        if (k0 < DD) {
            ph = g_x16 + ((size_t)t * BB + (m0 + row)) * DD + k0 + q * 8;
        } else {
            ph = hrd + (size_t)(m0 + row) * HH + (k0 - DD) + q * 8;
        }
        CP16(sb + SW(row * 128 + q * 16), ph);
    }
}

// ---------------- per-stage compute: 64-K slab vs resident W slab ----------------
__device__ __forceinline__ void compute_stage(uint32_t sbase, uint32_t sa, int slab,
                                              int lane, int m0w, int n0w,
                                              float acc[2][4][4])
{
    const int rowA = m0w + (lane & 15);
    const int colA = (lane >> 4) * 16;
    const int rowB = slab * 64 + n0w + (lane & 15);
    const int colB = (lane >> 4) * 16;

#pragma unroll
    for (int k16 = 0; k16 < 4; k16++) {
        uint32_t a[2][4];
#pragma unroll
        for (int mf = 0; mf < 2; mf++) {
            int off = (rowA + mf * 16) * 128 + colA + k16 * 32;
            LDSM_X4(a[mf][0], a[mf][1], a[mf][2], a[mf][3], sa + SW(off));
        }
        uint32_t w[4][2];
#pragma unroll
        for (int nn = 0; nn < 2; nn++) {
            int off = (rowB + nn * 16) * 128 + colB + k16 * 32;
            uint32_t r0, r1, r2, r3;
            LDSM_X4(r0, r1, r2, r3, sbase + OFF_W + SW(off));
            w[nn * 2 + 0][0] = r0; w[nn * 2 + 0][1] = r2;
            w[nn * 2 + 1][0] = r1; w[nn * 2 + 1][1] = r3;
        }
#pragma unroll
        for (int mf = 0; mf < 2; mf++)
#pragma unroll
            for (int nf = 0; nf < 4; nf++)
                MMA_F16(acc[mf][nf], a[mf], w[nf]);
    }
}

// ---------------- persistent LSTM kernel ----------------
__global__ void __launch_bounds__(NTH, 1) lstm_mma_kernel(
    const float* __restrict__ Wph, const float* __restrict__ bp, float* __restrict__ out)
{
    extern __shared__ char smem[];
    const uint32_t sbase = smem_to_u32(smem);
    const int tid  = threadIdx.x;
    const int wid  = tid >> 5;
    const int lane = tid & 31;
    const int m0w  = (wid >> 1) * 32;
    const int n0w  = (wid & 1) * 32;
    const int mt   = blockIdx.x >> 6;     // 0..1
    const int nt   = blockIdx.x & 63;     // 0..63
    const int m0   = mt * 128;
    const int n0   = nt * 64;
    const int j0   = nt * 16 + (n0w >> 2);
    const int gid  = lane >> 2;
    const int tid4 = lane & 3;
    unsigned* bar  = &g_barg[mt * 32];    // per-mt group barrier (64 CTAs)

#define SBUF(s) (sbase + OFF_AST + (uint32_t)(s) * STG_STRIDE)

    // ---- load resident W: 20 slabs x (64 rows x 128B), rows r = slab*64 + nl
#pragma unroll
    for (int i = 0; i < 40; i++) {
        int idx  = tid + i * NTH;         // 0..10239
        int r    = idx >> 3;              // 0..1279
        int q    = idx & 7;
        int slab = r >> 6;
        int nl   = r & 63;
        CP16(sbase + OFF_W + SW(r * 128 + q * 16),
             g_W16 + (size_t)(n0 + nl) * KTOT + slab * KBLK + q * 8);
    }
    CP_COMMIT();

    // x slabs 0..3 of t=0 (all k0 < DD, h not needed)
    stage_A(SBUF(0), 0, m0, 0 * KBLK, tid, g_h16[0]); CP_COMMIT();
    stage_A(SBUF(1), 0, m0, 1 * KBLK, tid, g_h16[0]); CP_COMMIT();
    stage_A(SBUF(2), 0, m0, 2 * KBLK, tid, g_h16[0]); CP_COMMIT();
    stage_A(SBUF(3), 0, m0, 3 * KBLK, tid, g_h16[0]); CP_COMMIT();

    // per-thread bias for owned (u2, gate) cells
    float biasr[2][4];
#pragma unroll
    for (int u2 = 0; u2 < 2; u2++)
#pragma unroll
        for (int g = 0; g < 4; g++) {
            int o = (u2 * 2 + (g >> 1)) * 8 + tid4 * 2 + (g & 1);
            biasr[u2][g] = g_bcat[n0 + n0w + o];
        }

    // c-state in registers
    float cst[2][2][2];
#pragma unroll
    for (int a = 0; a < 2; a++)
#pragma unroll
        for (int b = 0; b < 2; b++)
#pragma unroll
            for (int cdx = 0; cdx < 2; cdx++) cst[a][b][cdx] = 0.0f;

    float acc[2][4][4];
#pragma unroll
    for (int mf = 0; mf < 2; mf++)
#pragma unroll
        for (int nf = 0; nf < 4; nf++)
#pragma unroll
            for (int e = 0; e < 4; e++) acc[mf][nf][e] = 0.0f;

    // t=0 head: compute x slabs 0..3 (W group drains with the first WAIT3)
    CP_WAIT3(); __syncthreads();
    compute_stage(sbase, SBUF(0), 0, lane, m0w, n0w, acc);
    CP_WAIT2(); __syncthreads();
    compute_stage(sbase, SBUF(1), 1, lane, m0w, n0w, acc);
    CP_WAIT1(); __syncthreads();
    compute_stage(sbase, SBUF(2), 2, lane, m0w, n0w, acc);
    CP_WAIT0(); __syncthreads();
    compute_stage(sbase, SBUF(3), 3, lane, m0w, n0w, acc);

    for (int t = 0; t < TT; t++) {
        const int wb = (t & 1) ^ 1;
        const __half* hrd = g_h16[t & 1];
        const bool more = (t + 1 < TT);

        // h-dependent slabs 4,5,6 (slab k -> SBUF(k&3))
        stage_A(SBUF(0), t, m0, 4 * KBLK, tid, hrd); CP_COMMIT();
        stage_A(SBUF(1), t, m0, 5 * KBLK, tid, hrd); CP_COMMIT();
        stage_A(SBUF(2), t, m0, 6 * KBLK, tid, hrd); CP_COMMIT();

        // slabs 4..16: keep 3 in flight
        for (int kc = 4; kc < NKB - 3; kc++) {       // kc = 4..16
            CP_WAIT2();
            __syncthreads();
            compute_stage(sbase, SBUF(kc & 3), kc, lane, m0w, n0w, acc);
            stage_A(SBUF((kc + 3) & 3), t, m0, (kc + 3) * KBLK, tid, hrd);
            CP_COMMIT();
        }

        // tail: slabs 17,18,19 with t+1 x-slabs staged in the gaps
        // outstanding at entry: {17,18,19}
        CP_WAIT2(); __syncthreads();
        compute_stage(sbase, SBUF(17 & 3), 17, lane, m0w, n0w, acc);
        if (more) { stage_A(SBUF(0), t + 1, m0, 0 * KBLK, tid, hrd); CP_COMMIT(); }
        // outstanding: {18,19,x0} / {18,19}
        if (more) CP_WAIT2(); else CP_WAIT1();
        __syncthreads();
        compute_stage(sbase, SBUF(18 & 3), 18, lane, m0w, n0w, acc);
        if (more) { stage_A(SBUF(1), t + 1, m0, 1 * KBLK, tid, hrd); CP_COMMIT(); }
        // outstanding: {19,x0,x1} / {19}
        if (more) CP_WAIT2(); else CP_WAIT0();
        __syncthreads();
        compute_stage(sbase, SBUF(19 & 3), 19, lane, m0w, n0w, acc);
        if (more) { stage_A(SBUF(2), t + 1, m0, 2 * KBLK, tid, hrd); CP_COMMIT(); }
        // outstanding: {x0,x1,x2} / {}

        // gate math + state update, all in-register
#pragma unroll
        for (int mf = 0; mf < 2; mf++)
#pragma unroll
            for (int hr = 0; hr < 2; hr++) {
                const int m = m0 + m0w + mf * 16 + gid + hr * 8;
#pragma unroll
                for (int u2 = 0; u2 < 2; u2++) {
                    float pg = acc[mf][u2 * 2 + 0][hr * 2 + 0] + biasr[u2][0];
                    float pi = acc[mf][u2 * 2 + 0][hr * 2 + 1] + biasr[u2][1];
                    float pf = acc[mf][u2 * 2 + 1][hr * 2 + 0] + biasr[u2][2];
                    float po = acc[mf][u2 * 2 + 1][hr * 2 + 1] + biasr[u2][3];
                    float gt = tanhfast(pg);
                    float it = sigf(pi);
                    float ft = sigf(pf);
                    float ot = sigf(po);
                    float cn = gt * it + cst[mf][hr][u2] * ft;
                    cst[mf][hr][u2] = cn;
                    float hv = tanhfast(cn) * ot;
                    const int j = j0 + u2 * 4 + tid4;
                    size_t o = (size_t)m * HH + j;
                    g_h16[wb][o] = __float2half_rn(hv);
                    if (t == TT - 1) g_hf[o] = hv;
                }
            }

        // all threads' h writes + stage-buffer reads done
        __syncthreads();

        if (more) {
            stage_A(SBUF(3), t + 1, m0, 3 * KBLK, tid, hrd); CP_COMMIT();
            // outstanding: {x0,x1,x2,x3}
            grid_arrive(bar);

            // compute the 4 x-slabs of t+1 WHILE the group finishes step t
#pragma unroll
            for (int mf = 0; mf < 2; mf++)
#pragma unroll
                for (int nf = 0; nf < 4; nf++)
#pragma unroll
                    for (int e = 0; e < 4; e++) acc[mf][nf][e] = 0.0f;

            CP_WAIT3(); __syncthreads();
            compute_stage(sbase, SBUF(0), 0, lane, m0w, n0w, acc);
            CP_WAIT2(); __syncthreads();
            compute_stage(sbase, SBUF(1), 1, lane, m0w, n0w, acc);
            CP_WAIT1(); __syncthreads();
            compute_stage(sbase, SBUF(2), 2, lane, m0w, n0w, acc);
            CP_WAIT0(); __syncthreads();
            compute_stage(sbase, SBUF(3), 3, lane, m0w, n0w, acc);

            grid_wait(bar, (unsigned)(t + 1) * 64u);
        } else {
            // FINAL barrier: group g_hf writes must land before projection
            grid_arrive(bar);
            grid_wait(bar, (unsigned)TT * 64u);
        }
    }

    // final projection: out[b][cc] = g_hf[b] . Wph[:,cc] + bp[cc]
    // (rows read here belong to this CTA's own mt group)
    {
        const int gidx = blockIdx.x * NTH + tid;   // 0..32767 = 256 x 128
        const int b  = gidx >> 7;
        const int cc = gidx & 127;
        const float* hrow = g_hf + (size_t)b * HH;
        float s = 0.0f;
#pragma unroll 8
        for (int k = 0; k < HH; k++) s += hrow[k] * Wph[(size_t)k * CCC + cc];
        out[gidx] = s + bp[cc];
    }
#undef SBUF
}

// ---------------- launch ----------------
extern "C" void kernel_launch(void* const* d_in, const int* in_sizes, int n_in,
                              void* d_out, int out_size)
{
    (void)in_sizes; (void)n_in; (void)out_size;
    const float* x   = (const float*)d_in[0];
    const float* Wgx = (const float*)d_in[1];
    const float* Wgh = (const float*)d_in[2];
    const float* bg  = (const float*)d_in[3];
    const float* Wix = (const float*)d_in[4];
    const float* Wih = (const float*)d_in[5];
    const float* bi  = (const float*)d_in[6];
    const float* Wfx = (const float*)d_in[7];
    const float* Wfh = (const float*)d_in[8];
    const float* bf  = (const float*)d_in[9];
    const float* Wox = (const float*)d_in[10];
    const float* Woh = (const float*)d_in[11];
    const float* bo  = (const float*)d_in[12];
    const float* Wph = (const float*)d_in[13];
    const float* bp  = (const float*)d_in[14];

    cudaFuncSetAttribute(lstm_mma_kernel, cudaFuncAttributeMaxDynamicSharedMemorySize, SMEM_TOTAL);

    pack_w_kernel<<<512, 256>>>(Wgx, Wgh, Wix, Wih, Wfx, Wfh, Wox, Woh, bg, bi, bf, bo);
    pack_x_kernel<<<2048, 256>>>(x);
    lstm_mma_kernel<<<GRID, NTH, SMEM_TOTAL>>>(Wph, bp, (float*)d_out);
}

// round 17
// speedup vs baseline: 1.1745x; 1.1745x over previous
#include <cuda_runtime.h>
#include <cuda_fp16.h>
#include <math.h>
#include <stdint.h>

// LSTM B=256,T=512,D=256,H=1024,C=128.
// Persistent kernel on mma.sync fp16 (single fp16 W, fp16 A), fp32 accum.
// 128 CTAs = 2 Mtiles(128) x 64 Ntiles(64).
// R12 = R10 base (best) + fast-divide gate math + merged hidden-phase waits.

#define BB   256
#define TT   512
#define DD   256
#define HH   1024
#define CCC  128
#define KTOT 1280
#define NTOT 4096
#define GRID 128
#define NTH  256
#define KBLK 64
#define NKB  (KTOT / KBLK)   // 20

// dynamic smem: W resident (20 slabs x 8KB) + FOUR A stages (16KB each)
#define OFF_W      0
#define OFF_AST    163840
#define STG_STRIDE 16384
#define SMEM_TOTAL 229376    // 163840 + 4*16384

#define SW(o) ((o) ^ (((o) >> 3) & 0x70))

// ---------------- device globals ----------------
__device__ __half g_W16[(size_t)NTOT * KTOT];
__device__ float  g_bcat[NTOT];
__device__ __half g_x16[(size_t)TT * BB * DD];
__device__ __half g_h16[2][BB * HH];   // double-buffered across steps
__device__ float  g_hf[BB * HH];
__device__ unsigned g_bar;

// ---------------- PTX helpers ----------------
__device__ __forceinline__ uint32_t smem_to_u32(const void* p) {
    uint32_t a;
    asm("{ .reg .u64 t; cvta.to.shared.u64 t, %1; cvt.u32.u64 %0, t; }" : "=r"(a) : "l"(p));
    return a;
}

#define CP16(dst, src) \
    asm volatile("cp.async.cg.shared.global [%0], [%1], 16;" :: "r"(dst), "l"(src) : "memory")
#define CP_COMMIT() asm volatile("cp.async.commit_group;" ::: "memory")
#define CP_WAIT0()  asm volatile("cp.async.wait_group 0;" ::: "memory")
#define CP_WAIT1()  asm volatile("cp.async.wait_group 1;" ::: "memory")
#define CP_WAIT2()  asm volatile("cp.async.wait_group 2;" ::: "memory")
#define CP_WAIT3()  asm volatile("cp.async.wait_group 3;" ::: "memory")

#define LDSM_X4(r0, r1, r2, r3, addr) \
    asm volatile("ldmatrix.sync.aligned.m8n8.x4.shared.b16 {%0,%1,%2,%3}, [%4];" \
                 : "=r"(r0), "=r"(r1), "=r"(r2), "=r"(r3) : "r"(addr))

#define MMA_F16(c, a, b) \
    asm volatile("mma.sync.aligned.m16n8k16.row.col.f32.f16.f16.f32 " \
                 "{%0,%1,%2,%3},{%4,%5,%6,%7},{%8,%9},{%0,%1,%2,%3};" \
                 : "+f"((c)[0]), "+f"((c)[1]), "+f"((c)[2]), "+f"((c)[3]) \
                 : "r"((a)[0]), "r"((a)[1]), "r"((a)[2]), "r"((a)[3]), \
                   "r"((b)[0]), "r"((b)[1]))

// ---------------- column interleave mapping ----------------
// Within each 32-col warp tile: col(u,g) = 16*(u>>2) + 8*(g>>1) + 2*(u&3) + (g&1)
// => u = ((o>>4)<<2) + ((o>>1)&3),  g = ((o>>3)&1)*2 + (o&1)
// Global: n = w32*32 + o,  hidden j = w32*8 + u.

// ---------------- init kernels ----------------
__global__ void pack_w_kernel(
    const float* __restrict__ Wgx, const float* __restrict__ Wgh,
    const float* __restrict__ Wix, const float* __restrict__ Wih,
    const float* __restrict__ Wfx, const float* __restrict__ Wfh,
    const float* __restrict__ Wox, const float* __restrict__ Woh,
    const float* __restrict__ bg,  const float* __restrict__ bi,
    const float* __restrict__ bf,  const float* __restrict__ bo)
{
    const long total = (long)NTOT * KTOT;
    for (long idx = (long)blockIdx.x * blockDim.x + threadIdx.x; idx < total;
         idx += (long)gridDim.x * blockDim.x) {
        int n = (int)(idx / KTOT);
        int k = (int)(idx % KTOT);
        int o = n & 31;
        int w32 = n >> 5;
        int u = ((o >> 4) << 2) + ((o >> 1) & 3);
        int g = ((o >> 3) & 1) * 2 + (o & 1);
        int j = w32 * 8 + u;
        float w;
        if (k < DD) {
            const float* src = (g == 0) ? Wgx : (g == 1) ? Wix : (g == 2) ? Wfx : Wox;
            w = src[(size_t)k * HH + j];
        } else {
            const float* src = (g == 0) ? Wgh : (g == 1) ? Wih : (g == 2) ? Wfh : Woh;
            w = src[(size_t)(k - DD) * HH + j];
        }
        g_W16[idx] = __float2half_rn(w);

        if (idx < NTOT) {
            int nb  = (int)idx;
            int ob  = nb & 31;
            int wb  = nb >> 5;
            int ub  = ((ob >> 4) << 2) + ((ob >> 1) & 3);
            int gb  = ((ob >> 3) & 1) * 2 + (ob & 1);
            int jb  = wb * 8 + ub;
            const float* bsrc = (gb == 0) ? bg : (gb == 1) ? bi : (gb == 2) ? bf : bo;
            g_bcat[nb] = bsrc[jb];
        }
        if (idx < (long)BB * HH) {
            g_h16[0][idx] = __float2half_rn(0.0f);
            g_h16[1][idx] = __float2half_rn(0.0f);
        }
        if (idx == 0) g_bar = 0u;
    }
}

__global__ void pack_x_kernel(const float* __restrict__ x)
{
    const long total = (long)TT * BB * DD;
    for (long idx = (long)blockIdx.x * blockDim.x + threadIdx.x; idx < total;
         idx += (long)gridDim.x * blockDim.x) {
        int t = (int)(idx / (BB * DD));
        int r = (int)(idx % (BB * DD));
        int b = r / DD;
        int d = r % DD;
        g_x16[idx] = __float2half_rn(x[((size_t)b * TT + t) * DD + d]);
    }
}

// ---------------- split grid barrier ----------------
__device__ __forceinline__ void grid_arrive()
{
    // caller must __syncthreads() before this so all CTA writes precede release
    if (threadIdx.x == 0)
        asm volatile("red.release.gpu.global.add.u32 [%0], %1;" :: "l"(&g_bar), "r"(1u) : "memory");
}
__device__ __forceinline__ void grid_wait(unsigned target)
{
    if (threadIdx.x == 0) {
        unsigned v;
        do {
            asm volatile("ld.acquire.gpu.global.u32 %0, [%1];" : "=r"(v) : "l"(&g_bar) : "memory");
        } while (v < target);
    }
    __syncthreads();
}

// fast sigmoid/tanh: MUFU EX2 + MUFU RCP (rel err ~1e-7, numerically invisible
// against the 3.6e-4 fp16 quantization error; avoids full IEEE div sequences)
__device__ __forceinline__ float sigf(float x)
{
    return __fdividef(1.0f, 1.0f + __expf(-x));
}
__device__ __forceinline__ float tanhfast(float x) { return 2.0f * sigf(2.0f * x) - 1.0f; }

// ---------------- A staging: gmem -> smem via cp.async (A only) ----------------
__device__ __forceinline__ void stage_A(uint32_t sb, int t, int m0, int k0, int tid,
                                        const __half* __restrict__ hrd)
{
#pragma unroll
    for (int i = 0; i < 4; i++) {
        int idx = tid + i * NTH;       // 0..1023
        int row = idx >> 3;            // 0..127
        int q   = idx & 7;
        const __half* ph;
        if (k0 < DD) {
            ph = g_x16 + ((size_t)t * BB + (m0 + row)) * DD + k0 + q * 8;
        } else {
            ph = hrd + (size_t)(m0 + row) * HH + (k0 - DD) + q * 8;
        }
        CP16(sb + SW(row * 128 + q * 16), ph);
    }
}

// ---------------- per-stage compute: 64-K slab vs resident W slab ----------------
__device__ __forceinline__ void compute_stage(uint32_t sbase, uint32_t sa, int slab,
                                              int lane, int m0w, int n0w,
                                              float acc[2][4][4])
{
    const int rowA = m0w + (lane & 15);
    const int colA = (lane >> 4) * 16;
    const int rowB = slab * 64 + n0w + (lane & 15);
    const int colB = (lane >> 4) * 16;

#pragma unroll
    for (int k16 = 0; k16 < 4; k16++) {
        uint32_t a[2][4];
#pragma unroll
        for (int mf = 0; mf < 2; mf++) {
            int off = (rowA + mf * 16) * 128 + colA + k16 * 32;
            LDSM_X4(a[mf][0], a[mf][1], a[mf][2], a[mf][3], sa + SW(off));
        }
        uint32_t w[4][2];
#pragma unroll
        for (int nn = 0; nn < 2; nn++) {
            int off = (rowB + nn * 16) * 128 + colB + k16 * 32;
            uint32_t r0, r1, r2, r3;
            LDSM_X4(r0, r1, r2, r3, sbase + OFF_W + SW(off));
            w[nn * 2 + 0][0] = r0; w[nn * 2 + 0][1] = r2;
            w[nn * 2 + 1][0] = r1; w[nn * 2 + 1][1] = r3;
        }
#pragma unroll
        for (int mf = 0; mf < 2; mf++)
#pragma unroll
            for (int nf = 0; nf < 4; nf++)
                MMA_F16(acc[mf][nf], a[mf], w[nf]);
    }
}

// ---------------- persistent LSTM kernel ----------------
__global__ void __launch_bounds__(NTH, 1) lstm_mma_kernel(
    const float* __restrict__ Wph, const float* __restrict__ bp, float* __restrict__ out)
{
    extern __shared__ char smem[];
    const uint32_t sbase = smem_to_u32(smem);
    const int tid  = threadIdx.x;
    const int wid  = tid >> 5;
    const int lane = tid & 31;
    const int m0w  = (wid >> 1) * 32;
    const int n0w  = (wid & 1) * 32;
    const int mt   = blockIdx.x >> 6;     // 0..1
    const int nt   = blockIdx.x & 63;     // 0..63
    const int m0   = mt * 128;
    const int n0   = nt * 64;
    const int j0   = nt * 16 + (n0w >> 2);
    const int gid  = lane >> 2;
    const int tid4 = lane & 3;

#define SBUF(s) (sbase + OFF_AST + (uint32_t)(s) * STG_STRIDE)

    // ---- load resident W: 20 slabs x (64 rows x 128B), rows r = slab*64 + nl
#pragma unroll
    for (int i = 0; i < 40; i++) {
        int idx  = tid + i * NTH;         // 0..10239
        int r    = idx >> 3;              // 0..1279
        int q    = idx & 7;
        int slab = r >> 6;
        int nl   = r & 63;
        CP16(sbase + OFF_W + SW(r * 128 + q * 16),
             g_W16 + (size_t)(n0 + nl) * KTOT + slab * KBLK + q * 8);
    }
    CP_COMMIT();

    // x slabs 0..3 of t=0 (all k0 < DD, h not needed)
    stage_A(SBUF(0), 0, m0, 0 * KBLK, tid, g_h16[0]); CP_COMMIT();
    stage_A(SBUF(1), 0, m0, 1 * KBLK, tid, g_h16[0]); CP_COMMIT();
    stage_A(SBUF(2), 0, m0, 2 * KBLK, tid, g_h16[0]); CP_COMMIT();
    stage_A(SBUF(3), 0, m0, 3 * KBLK, tid, g_h16[0]); CP_COMMIT();

    // per-thread bias for owned (u2, gate) cells
    float biasr[2][4];
#pragma unroll
    for (int u2 = 0; u2 < 2; u2++)
#pragma unroll
        for (int g = 0; g < 4; g++) {
            int o = (u2 * 2 + (g >> 1)) * 8 + tid4 * 2 + (g & 1);
            biasr[u2][g] = g_bcat[n0 + n0w + o];
        }

    // c-state in registers
    float cst[2][2][2];
#pragma unroll
    for (int a = 0; a < 2; a++)
#pragma unroll
        for (int b = 0; b < 2; b++)
#pragma unroll
            for (int cdx = 0; cdx < 2; cdx++) cst[a][b][cdx] = 0.0f;

    float acc[2][4][4];
#pragma unroll
    for (int mf = 0; mf < 2; mf++)
#pragma unroll
        for (int nf = 0; nf < 4; nf++)
#pragma unroll
            for (int e = 0; e < 4; e++) acc[mf][nf][e] = 0.0f;

    // t=0 head: wait for W + all 4 x-slabs at once, then compute them
    CP_WAIT0(); __syncthreads();
    compute_stage(sbase, SBUF(0), 0, lane, m0w, n0w, acc);
    compute_stage(sbase, SBUF(1), 1, lane, m0w, n0w, acc);
    compute_stage(sbase, SBUF(2), 2, lane, m0w, n0w, acc);
    compute_stage(sbase, SBUF(3), 3, lane, m0w, n0w, acc);

    for (int t = 0; t < TT; t++) {
        const int wb = (t & 1) ^ 1;
        const __half* hrd = g_h16[t & 1];

        // h-dependent slabs 4,5,6 (slab k -> SBUF(k&3))
        stage_A(SBUF(0), t, m0, 4 * KBLK, tid, hrd); CP_COMMIT();
        stage_A(SBUF(1), t, m0, 5 * KBLK, tid, hrd); CP_COMMIT();
        stage_A(SBUF(2), t, m0, 6 * KBLK, tid, hrd); CP_COMMIT();

        // slabs 4..16: keep 3 in flight
        for (int kc = 4; kc < NKB - 3; kc++) {       // kc = 4..16
            CP_WAIT2();
            __syncthreads();
            compute_stage(sbase, SBUF(kc & 3), kc, lane, m0w, n0w, acc);
            stage_A(SBUF((kc + 3) & 3), t, m0, (kc + 3) * KBLK, tid, hrd);
            CP_COMMIT();
        }
        CP_WAIT2(); __syncthreads();
        compute_stage(sbase, SBUF(17 & 3), 17, lane, m0w, n0w, acc);
        CP_WAIT1(); __syncthreads();
        compute_stage(sbase, SBUF(18 & 3), 18, lane, m0w, n0w, acc);
        CP_WAIT0(); __syncthreads();
        compute_stage(sbase, SBUF(19 & 3), 19, lane, m0w, n0w, acc);

        // gate math + state update, all in-register
#pragma unroll
        for (int mf = 0; mf < 2; mf++)
#pragma unroll
            for (int hr = 0; hr < 2; hr++) {
                const int m = m0 + m0w + mf * 16 + gid + hr * 8;
#pragma unroll
                for (int u2 = 0; u2 < 2; u2++) {
                    float pg = acc[mf][u2 * 2 + 0][hr * 2 + 0] + biasr[u2][0];
                    float pi = acc[mf][u2 * 2 + 0][hr * 2 + 1] + biasr[u2][1];
                    float pf = acc[mf][u2 * 2 + 1][hr * 2 + 0] + biasr[u2][2];
                    float po = acc[mf][u2 * 2 + 1][hr * 2 + 1] + biasr[u2][3];
                    float gt = tanhfast(pg);
                    float it = sigf(pi);
                    float ft = sigf(pf);
                    float ot = sigf(po);
                    float cn = gt * it + cst[mf][hr][u2] * ft;
                    cst[mf][hr][u2] = cn;
                    float hv = tanhfast(cn) * ot;
                    const int j = j0 + u2 * 4 + tid4;
                    size_t o = (size_t)m * HH + j;
                    g_h16[wb][o] = __float2half_rn(hv);
                    if (t == TT - 1) g_hf[o] = hv;
                }
            }

        // all threads' h writes + stage-buffer reads done
        __syncthreads();

        if (t + 1 < TT) {
            // prefetch the 4 x-slabs of t+1, announce arrival, compute them
            // WHILE other CTAs finish step t, then wait.
            stage_A(SBUF(0), t + 1, m0, 0 * KBLK, tid, hrd); CP_COMMIT();
            stage_A(SBUF(1), t + 1, m0, 1 * KBLK, tid, hrd); CP_COMMIT();
            stage_A(SBUF(2), t + 1, m0, 2 * KBLK, tid, hrd); CP_COMMIT();
            stage_A(SBUF(3), t + 1, m0, 3 * KBLK, tid, hrd); CP_COMMIT();
            grid_arrive();

#pragma unroll
            for (int mf = 0; mf < 2; mf++)
#pragma unroll
                for (int nf = 0; nf < 4; nf++)
#pragma unroll
                    for (int e = 0; e < 4; e++) acc[mf][nf][e] = 0.0f;

            // single wait for all 4 groups (issued long ago), one sync,
            // then one uninterrupted 4-slab HMMA run
            CP_WAIT0(); __syncthreads();
            compute_stage(sbase, SBUF(0), 0, lane, m0w, n0w, acc);
            compute_stage(sbase, SBUF(1), 1, lane, m0w, n0w, acc);
            compute_stage(sbase, SBUF(2), 2, lane, m0w, n0w, acc);
            compute_stage(sbase, SBUF(3), 3, lane, m0w, n0w, acc);

            grid_wait((unsigned)(t + 1) * GRID);
        } else {
            // FINAL barrier: all CTAs' g_hf writes must land before the
            // projection reads the full h rows.
            grid_arrive();
            grid_wait((unsigned)TT * GRID);
        }
    }

    // final projection: out[b][cc] = g_hf[b] . Wph[:,cc] + bp[cc]
    {
        const int gidx = blockIdx.x * NTH + tid;   // 0..32767 = 256 x 128
        const int b  = gidx >> 7;
        const int cc = gidx & 127;
        const float* hrow = g_hf + (size_t)b * HH;
        float s = 0.0f;
#pragma unroll 8
        for (int k = 0; k < HH; k++) s += hrow[k] * Wph[(size_t)k * CCC + cc];
        out[gidx] = s + bp[cc];
    }
#undef SBUF
}

// ---------------- launch ----------------
extern "C" void kernel_launch(void* const* d_in, const int* in_sizes, int n_in,
                              void* d_out, int out_size)
{
    (void)in_sizes; (void)n_in; (void)out_size;
    const float* x   = (const float*)d_in[0];
    const float* Wgx = (const float*)d_in[1];
    const float* Wgh = (const float*)d_in[2];
    const float* bg  = (const float*)d_in[3];
    const float* Wix = (const float*)d_in[4];
    const float* Wih = (const float*)d_in[5];
    const float* bi  = (const float*)d_in[6];
    const float* Wfx = (const float*)d_in[7];
    const float* Wfh = (const float*)d_in[8];
    const float* bf  = (const float*)d_in[9];
    const float* Wox = (const float*)d_in[10];
    const float* Woh = (const float*)d_in[11];
    const float* bo  = (const float*)d_in[12];
    const float* Wph = (const float*)d_in[13];
    const float* bp  = (const float*)d_in[14];

    cudaFuncSetAttribute(lstm_mma_kernel, cudaFuncAttributeMaxDynamicSharedMemorySize, SMEM_TOTAL);

    pack_w_kernel<<<512, 256>>>(Wgx, Wgh, Wix, Wih, Wfx, Wfh, Wox, Woh, bg, bi, bf, bo);
    pack_x_kernel<<<2048, 256>>>(x);
    lstm_mma_kernel<<<GRID, NTH, SMEM_TOTAL>>>(Wph, bp, (float*)d_out);
}